// round 14
// baseline (speedup 1.0000x reference)
#include <cuda_runtime.h>
#include <cuda_bf16.h>
#include <cuda_fp16.h>

// Problem constants (EdgeConv_33930241638504): N=50000, E=800000, IN=OUT=16, T=8
#define MAXN 50048
#define IN_F 16
#define OUT_F 16
#define T_F 8
#define LN_EPS 1e-5f
#define BSHIFT 6                    // bucket = src >> 6  (64-node window)
#define NBUCK_MAX 1024              // >= (MAXN >> BSHIFT)
#define BCAP 2048                   // bucket capacity (mean ~1023, sigma ~32)

// Scratch (device globals: allocation-free rule)
// g fp16, 256B/node, layout [n][j=t/2][o][s=t&1]: half idx = n*128 + j*32 + o*2 + s.
__device__ __half   g_gh[(size_t)MAXN * 128];   // 12.8 MB
__device__ float    g_c[MAXN * OUT_F];          // 3.2 MB
__device__ int      g_idx64;                    // 1 if edge_index int64, 0 if int32
__device__ unsigned g_cur[NBUCK_MAX];           // bucket cursors
__device__ uint4    g_rec[(size_t)NBUCK_MAX * BCAP * 2];  // 32B records (67 MB)

// ---------------------------------------------------------------------------
// Kernel 1: per-node preprocessing, 4 nodes per 16-lane group (register-blocked)
// + dtype detection + bucket-cursor zeroing.
// ---------------------------------------------------------------------------
#define OPAD 20
#define NPB 64   // nodes per block
__global__ __launch_bounds__(256, 2) void node_kernel(
    const float* __restrict__ x,
    const float* __restrict__ ln_gamma,
    const float* __restrict__ ln_beta,
    const float* __restrict__ w_edge,   // [T, IN*OUT]
    const float* __restrict__ b_edge,   // [IN*OUT]
    const float* __restrict__ root,     // [IN, OUT]
    const float* __restrict__ bias,     // [OUT]
    const unsigned int* __restrict__ idx_raw,
    float* __restrict__ out,
    int N)
{
    __shared__ float Wt[T_F * IN_F * OPAD];   // [t][o*20 + i]
    __shared__ float Bt[IN_F * OPAD];
    __shared__ float Rt[IN_F * OPAD];
    __shared__ __half Gs[NPB * 128];

    for (int idx = threadIdx.x; idx < T_F * IN_F * OUT_F; idx += blockDim.x) {
        int t = idx >> 8, rem = idx & 255, i = rem >> 4, o = rem & 15;
        Wt[t * (IN_F * OPAD) + o * OPAD + i] = w_edge[idx];
    }
    for (int idx = threadIdx.x; idx < IN_F * OUT_F; idx += blockDim.x) {
        int i = idx >> 4, o = idx & 15;
        Bt[o * OPAD + i] = b_edge[idx];
        Rt[o * OPAD + i] = root[idx];
    }

    int gtid = blockIdx.x * blockDim.x + threadIdx.x;
    if (gtid < NBUCK_MAX) g_cur[gtid] = 0u;   // zero cursors for scatter_kernel

    // dtype detection (block 0, warp 0): int64 LE with values < N => odd words zero.
    if (blockIdx.x == 0 && threadIdx.x < 32) {
        int lane = threadIdx.x;
        unsigned int any = 0;
        #pragma unroll
        for (int k = 0; k < 8; k++) any |= idx_raw[2 * (lane * 8 + k) + 1];
        unsigned int ballot = __ballot_sync(0xffffffffu, any != 0);
        if (lane == 0) g_idx64 = (ballot == 0u) ? 1 : 0;
    }
    __syncthreads();

    int gidx = threadIdx.x >> 4;        // group 0..15
    int o    = threadIdx.x & 15;
    int nb0  = blockIdx.x * NPB + gidx * 4;

    float h_own[4];
    #pragma unroll
    for (int k = 0; k < 4; k++) {
        int n = nb0 + k;
        if (n >= N) n = N - 1;
        float xv = x[(size_t)n * IN_F + o];
        float s = xv;
        #pragma unroll
        for (int off = 8; off > 0; off >>= 1) s += __shfl_xor_sync(0xffffffffu, s, off, 16);
        float mu = s * (1.0f / 16.0f);
        float d = xv - mu;
        float v = d * d;
        #pragma unroll
        for (int off = 8; off > 0; off >>= 1) v += __shfl_xor_sync(0xffffffffu, v, off, 16);
        float rstd = rsqrtf(v * (1.0f / 16.0f) + LN_EPS);
        float h = d * rstd * ln_gamma[o] + ln_beta[o];
        h_own[k] = fmaxf(h, 0.0f);
    }

    float hv[4][IN_F];
    #pragma unroll
    for (int k = 0; k < 4; k++) {
        #pragma unroll
        for (int i = 0; i < IN_F; i++)
            hv[k][i] = __shfl_sync(0xffffffffu, h_own[k], i, 16);
    }

    #pragma unroll
    for (int t = 0; t < T_F; t++) {
        const float4* wrow = (const float4*)&Wt[t * (IN_F * OPAD) + o * OPAD];
        float4 w0 = wrow[0], w1 = wrow[1], w2 = wrow[2], w3 = wrow[3];
        #pragma unroll
        for (int k = 0; k < 4; k++) {
            float acc = 0.0f;
            acc = fmaf(hv[k][0],  w0.x, acc); acc = fmaf(hv[k][1],  w0.y, acc);
            acc = fmaf(hv[k][2],  w0.z, acc); acc = fmaf(hv[k][3],  w0.w, acc);
            acc = fmaf(hv[k][4],  w1.x, acc); acc = fmaf(hv[k][5],  w1.y, acc);
            acc = fmaf(hv[k][6],  w1.z, acc); acc = fmaf(hv[k][7],  w1.w, acc);
            acc = fmaf(hv[k][8],  w2.x, acc); acc = fmaf(hv[k][9],  w2.y, acc);
            acc = fmaf(hv[k][10], w2.z, acc); acc = fmaf(hv[k][11], w2.w, acc);
            acc = fmaf(hv[k][12], w3.x, acc); acc = fmaf(hv[k][13], w3.y, acc);
            acc = fmaf(hv[k][14], w3.z, acc); acc = fmaf(hv[k][15], w3.w, acc);
            Gs[(gidx * 4 + k) * 128 + (t >> 1) * 32 + o * 2 + (t & 1)] = __float2half(acc);
        }
    }

    {
        const float4* brow = (const float4*)&Bt[o * OPAD];
        float4 b0 = brow[0], b1 = brow[1], b2 = brow[2], b3 = brow[3];
        const float4* rrow = (const float4*)&Rt[o * OPAD];
        float4 r0 = rrow[0], r1 = rrow[1], r2 = rrow[2], r3 = rrow[3];
        float bs = bias[o];
        #pragma unroll
        for (int k = 0; k < 4; k++) {
            int n = nb0 + k;
            bool valid = (n < N);
            float cb = 0.0f, cr = bs;
            cb = fmaf(hv[k][0],  b0.x, cb); cr = fmaf(hv[k][0],  r0.x, cr);
            cb = fmaf(hv[k][1],  b0.y, cb); cr = fmaf(hv[k][1],  r0.y, cr);
            cb = fmaf(hv[k][2],  b0.z, cb); cr = fmaf(hv[k][2],  r0.z, cr);
            cb = fmaf(hv[k][3],  b0.w, cb); cr = fmaf(hv[k][3],  r0.w, cr);
            cb = fmaf(hv[k][4],  b1.x, cb); cr = fmaf(hv[k][4],  r1.x, cr);
            cb = fmaf(hv[k][5],  b1.y, cb); cr = fmaf(hv[k][5],  r1.y, cr);
            cb = fmaf(hv[k][6],  b1.z, cb); cr = fmaf(hv[k][6],  r1.z, cr);
            cb = fmaf(hv[k][7],  b1.w, cb); cr = fmaf(hv[k][7],  r1.w, cr);
            cb = fmaf(hv[k][8],  b2.x, cb); cr = fmaf(hv[k][8],  r2.x, cr);
            cb = fmaf(hv[k][9],  b2.y, cb); cr = fmaf(hv[k][9],  r2.y, cr);
            cb = fmaf(hv[k][10], b2.z, cb); cr = fmaf(hv[k][10], r2.z, cr);
            cb = fmaf(hv[k][11], b2.w, cb); cr = fmaf(hv[k][11], r2.w, cr);
            cb = fmaf(hv[k][12], b3.x, cb); cr = fmaf(hv[k][12], r3.x, cr);
            cb = fmaf(hv[k][13], b3.y, cb); cr = fmaf(hv[k][13], r3.y, cr);
            cb = fmaf(hv[k][14], b3.z, cb); cr = fmaf(hv[k][14], r3.z, cr);
            cb = fmaf(hv[k][15], b3.w, cb); cr = fmaf(hv[k][15], r3.w, cr);
            if (valid) {
                g_c[(size_t)n * OUT_F + o] = cb;
                out[(size_t)n * OUT_F + o] = cr;
            }
        }
    }
    __syncthreads();

    {
        const uint4* src = (const uint4*)Gs;
        uint4* dst = (uint4*)(g_gh + (size_t)blockIdx.x * NPB * 128);
        #pragma unroll
        for (int kk = 0; kk < 4; kk++) {
            int u = kk * 256 + threadIdx.x;
            int nd = blockIdx.x * NPB + (u >> 4);
            if (nd < N) dst[u] = src[u];
        }
    }
}

// ---------------------------------------------------------------------------
// Kernel 2: bucket edges by src>>BSHIFT. Record (32B, 24 used):
//   {src, dst, ea[0..3] as 2x half2, ea[4..7] as 2x half2}
// ---------------------------------------------------------------------------
__global__ __launch_bounds__(256) void scatter_kernel(
    const void* __restrict__ edge_index,
    const float* __restrict__ edge_attr,
    int E)
{
    int e = blockIdx.x * blockDim.x + threadIdx.x;
    if (e >= E) return;

    int src, dst;
    if (g_idx64) {
        const long long* ei = (const long long*)edge_index;
        src = (int)ei[e];
        dst = (int)ei[(long)E + e];
    } else {
        const int* ei = (const int*)edge_index;
        src = ei[e];
        dst = ei[E + e];
    }

    const float4* eap = (const float4*)(edge_attr + (long)e * T_F);
    float4 e0 = eap[0];
    float4 e1 = eap[1];
    __half2 h01 = __floats2half2_rn(e0.x, e0.y);
    __half2 h23 = __floats2half2_rn(e0.z, e0.w);
    __half2 h45 = __floats2half2_rn(e1.x, e1.y);
    __half2 h67 = __floats2half2_rn(e1.z, e1.w);

    unsigned b = (unsigned)src >> BSHIFT;
    unsigned slot = atomicAdd(&g_cur[b], 1u);
    if (slot < BCAP) {
        size_t rbase = ((size_t)b * BCAP + slot) * 2;
        uint4 lo;
        lo.x = (unsigned)src;
        lo.y = (unsigned)dst;
        lo.z = *(unsigned*)&h01;
        lo.w = *(unsigned*)&h23;
        g_rec[rbase] = lo;
        uint2 hi;
        hi.x = *(unsigned*)&h45;
        hi.y = *(unsigned*)&h67;
        *(uint2*)&g_rec[rbase + 1] = hi;
    }
}

// ---------------------------------------------------------------------------
// Kernel 3: per-bucket edge processing. One CTA per bucket; the bucket's
// g window (64 nodes x 256B = 16KB) + c (4KB) stay L1-resident, so the
// 16x-redundant gather hits L1 instead of L2.
// 4 lanes per edge; lane q owns outputs [4q, 4q+4).
// ---------------------------------------------------------------------------
__global__ __launch_bounds__(256) void edge2_kernel(float* __restrict__ out)
{
    int b = blockIdx.x;
    unsigned cntu = g_cur[b];
    int cnt = (cntu < BCAP) ? (int)cntu : BCAP;

    int q = threadIdx.x & 3;
    const float4* c4 = (const float4*)g_c;

    for (int base = 0; base < cnt; base += 64) {
        int p = base + (threadIdx.x >> 2);
        if (p >= cnt) break;

        const uint4* rp = g_rec + ((size_t)b * BCAP + p) * 2;
        uint4 lo = rp[0];
        uint2 hi = *(const uint2*)(rp + 1);
        int src = (int)lo.x;
        int dst = (int)lo.y;

        float2 a01 = __half22float2(*(__half2*)&lo.z);
        float2 a23 = __half22float2(*(__half2*)&lo.w);
        float2 a45 = __half22float2(*(__half2*)&hi.x);
        float2 a67 = __half22float2(*(__half2*)&hi.y);
        float eat[T_F] = {a01.x, a01.y, a23.x, a23.y, a45.x, a45.y, a67.x, a67.y};

        float4 m = c4[src * 4 + q];

        const uint4* g4 = (const uint4*)(g_gh + (size_t)src * 128);
        #pragma unroll
        for (int j = 0; j < 4; j++) {
            uint4 u = g4[j * 4 + q];
            float b0 = eat[2 * j], b1 = eat[2 * j + 1];
            float2 pp;
            pp = __half22float2(*(const __half2*)&u.x);
            m.x = fmaf(b0, pp.x, fmaf(b1, pp.y, m.x));
            pp = __half22float2(*(const __half2*)&u.y);
            m.y = fmaf(b0, pp.x, fmaf(b1, pp.y, m.y));
            pp = __half22float2(*(const __half2*)&u.z);
            m.z = fmaf(b0, pp.x, fmaf(b1, pp.y, m.z));
            pp = __half22float2(*(const __half2*)&u.w);
            m.w = fmaf(b0, pp.x, fmaf(b1, pp.y, m.w));
        }

        float* dp = out + (size_t)dst * OUT_F + q * 4;
        asm volatile("red.global.add.v4.f32 [%0], {%1, %2, %3, %4};"
                     :: "l"(dp), "f"(m.x), "f"(m.y), "f"(m.z), "f"(m.w)
                     : "memory");
    }
}

// ---------------------------------------------------------------------------
extern "C" void kernel_launch(void* const* d_in, const int* in_sizes, int n_in,
                              void* d_out, int out_size)
{
    const float* x        = (const float*)d_in[0];
    const void*  eidx     = d_in[1];
    const float* eattr    = (const float*)d_in[2];
    const float* ln_gamma = (const float*)d_in[3];
    const float* ln_beta  = (const float*)d_in[4];
    const float* w_edge   = (const float*)d_in[5];
    const float* b_edge   = (const float*)d_in[6];
    const float* root     = (const float*)d_in[7];
    const float* bias     = (const float*)d_in[8];
    float* out = (float*)d_out;

    int N = in_sizes[0] / IN_F;
    int E = in_sizes[1] / 2;
    int nbuckets = (N + 63) >> BSHIFT;   // 782 for N=50000

    node_kernel<<<(N + NPB - 1) / NPB, 256>>>(x, ln_gamma, ln_beta, w_edge, b_edge,
                                              root, bias, (const unsigned int*)eidx,
                                              out, N);
    scatter_kernel<<<(E + 255) / 256, 256>>>(eidx, eattr, E);
    edge2_kernel<<<nbuckets, 256>>>(out);
}

// round 15
// speedup vs baseline: 1.7169x; 1.7169x over previous
#include <cuda_runtime.h>
#include <cuda_bf16.h>
#include <cuda_fp16.h>

// Problem constants (EdgeConv_33930241638504): N=50000, E=800000, IN=OUT=16, T=8
#define MAXN 50048
#define IN_F 16
#define OUT_F 16
#define T_F 8
#define LN_EPS 1e-5f

// Scratch (device globals: allocation-free rule)
// g fp16, 256B/node, layout [n][j=t/2][o][s=t&1]: half idx = n*128 + j*32 + o*2 + s.
__device__ __half g_gh[(size_t)MAXN * 128];   // 12.8 MB (L2-resident)
__device__ __half g_ch[(size_t)MAXN * 16];    // c[n][o] fp16 (1.6 MB, L2-resident)
__device__ int    g_idx64;                    // 1 if edge_index int64, 0 if int32

// packed f32x2 helpers (ptxas never emits FFMA2 from C++; PTX-only)
__device__ __forceinline__ void fma2(unsigned long long& acc,
                                     unsigned long long a, unsigned long long b)
{
    asm("fma.rn.f32x2 %0, %1, %2, %0;" : "+l"(acc) : "l"(a), "l"(b));
}
__device__ __forceinline__ unsigned long long pack2(float lo, float hi)
{
    unsigned long long v;
    asm("mov.b64 %0, {%1, %2};" : "=l"(v) : "f"(lo), "f"(hi));
    return v;
}
__device__ __forceinline__ void unpack2(unsigned long long v, float& lo, float& hi)
{
    asm("mov.b64 {%0, %1}, %2;" : "=f"(lo), "=f"(hi) : "l"(v));
}

// ---------------------------------------------------------------------------
// Kernel 1: per-node preprocessing, 4 nodes per 16-lane group, f32x2-packed.
// Nodes (0,1) and (2,3) share 64-bit accumulators; W/B/R stored in smem
// pre-duplicated as (w,w) float2 so LDS.64 feeds fma.rn.f32x2 directly.
//   g[n,t,o] = sum_i h[i]*W[t,i,o]    (fp16, staged via smem -> coalesced copy)
//   c[n,o]   = sum_i h[i]*b_edge[i,o] (fp16 table)
//   out[n,o] = sum_i h[i]*root[i,o] + bias[o]
// ---------------------------------------------------------------------------
#define IPAD 17   // float2 stride per o-row (conflict-free: bank = 2o + 2i mod 32)
#define NPB 64    // nodes per block
__global__ __launch_bounds__(256, 2) void node_kernel(
    const float* __restrict__ x,
    const float* __restrict__ ln_gamma,
    const float* __restrict__ ln_beta,
    const float* __restrict__ w_edge,   // [T, IN*OUT]
    const float* __restrict__ b_edge,   // [IN*OUT]
    const float* __restrict__ root,     // [IN, OUT]
    const float* __restrict__ bias,     // [OUT]
    const unsigned int* __restrict__ idx_raw,
    float* __restrict__ out,
    int N)
{
    __shared__ float2 Wt2[T_F * IN_F * IPAD];   // [t][o*17 + i] dup pairs ~17.4 KB
    __shared__ float2 Bt2[IN_F * IPAD];
    __shared__ float2 Rt2[IN_F * IPAD];
    __shared__ __half Gs[NPB * 128];            // 16 KB staged g

    for (int idx = threadIdx.x; idx < T_F * IN_F * OUT_F; idx += blockDim.x) {
        int t = idx >> 8, rem = idx & 255, i = rem >> 4, o = rem & 15;
        float w = w_edge[idx];
        Wt2[t * (IN_F * IPAD) + o * IPAD + i] = make_float2(w, w);
    }
    for (int idx = threadIdx.x; idx < IN_F * OUT_F; idx += blockDim.x) {
        int i = idx >> 4, o = idx & 15;
        float b = b_edge[idx], r = root[idx];
        Bt2[o * IPAD + i] = make_float2(b, b);
        Rt2[o * IPAD + i] = make_float2(r, r);
    }

    // dtype detection (block 0, warp 0): int64 LE with values < N => odd words zero.
    if (blockIdx.x == 0 && threadIdx.x < 32) {
        int lane = threadIdx.x;
        unsigned int any = 0;
        #pragma unroll
        for (int k = 0; k < 8; k++) any |= idx_raw[2 * (lane * 8 + k) + 1];
        unsigned int ballot = __ballot_sync(0xffffffffu, any != 0);
        if (lane == 0) g_idx64 = (ballot == 0u) ? 1 : 0;
    }
    __syncthreads();

    int gidx = threadIdx.x >> 4;        // group 0..15
    int o    = threadIdx.x & 15;        // lane = output/feature idx
    int nb0  = blockIdx.x * NPB + gidx * 4;

    // LN for the group's 4 nodes
    float h_own[4];
    #pragma unroll
    for (int k = 0; k < 4; k++) {
        int n = nb0 + k;
        if (n >= N) n = N - 1;
        float xv = x[(size_t)n * IN_F + o];
        float s = xv;
        #pragma unroll
        for (int off = 8; off > 0; off >>= 1) s += __shfl_xor_sync(0xffffffffu, s, off, 16);
        float mu = s * (1.0f / 16.0f);
        float d = xv - mu;
        float v = d * d;
        #pragma unroll
        for (int off = 8; off > 0; off >>= 1) v += __shfl_xor_sync(0xffffffffu, v, off, 16);
        float rstd = rsqrtf(v * (1.0f / 16.0f) + LN_EPS);
        float h = d * rstd * ln_gamma[o] + ln_beta[o];
        h_own[k] = fmaxf(h, 0.0f);
    }

    // h vectors packed as node-pairs: hp[p][i] = (h[2p][i], h[2p+1][i])
    unsigned long long hp[2][IN_F];
    #pragma unroll
    for (int p = 0; p < 2; p++) {
        #pragma unroll
        for (int i = 0; i < IN_F; i++) {
            float lo = __shfl_sync(0xffffffffu, h_own[2 * p], i, 16);
            float hi = __shfl_sync(0xffffffffu, h_own[2 * p + 1], i, 16);
            hp[p][i] = pack2(lo, hi);
        }
    }

    // g: per t, 16 LDS.64 feed 2 packed accumulators (4 nodes)
    #pragma unroll
    for (int t = 0; t < T_F; t++) {
        const float2* wrow = &Wt2[t * (IN_F * IPAD) + o * IPAD];
        unsigned long long acc0 = 0ull, acc1 = 0ull;
        #pragma unroll
        for (int i = 0; i < IN_F; i++) {
            unsigned long long w = *(const unsigned long long*)&wrow[i];
            fma2(acc0, hp[0][i], w);
            fma2(acc1, hp[1][i], w);
        }
        float f0, f1, f2, f3;
        unpack2(acc0, f0, f1);
        unpack2(acc1, f2, f3);
        int gbase = (t >> 1) * 32 + o * 2 + (t & 1);
        Gs[(gidx * 4 + 0) * 128 + gbase] = __float2half(f0);
        Gs[(gidx * 4 + 1) * 128 + gbase] = __float2half(f1);
        Gs[(gidx * 4 + 2) * 128 + gbase] = __float2half(f2);
        Gs[(gidx * 4 + 3) * 128 + gbase] = __float2half(f3);
    }

    // c (fp16 table) and out (fp32)
    {
        unsigned long long cb0 = 0ull, cb1 = 0ull, cr0 = 0ull, cr1 = 0ull;
        #pragma unroll
        for (int i = 0; i < IN_F; i++) {
            unsigned long long b = *(const unsigned long long*)&Bt2[o * IPAD + i];
            unsigned long long r = *(const unsigned long long*)&Rt2[o * IPAD + i];
            fma2(cb0, hp[0][i], b);
            fma2(cb1, hp[1][i], b);
            fma2(cr0, hp[0][i], r);
            fma2(cr1, hp[1][i], r);
        }
        float bs = bias[o];
        float cbf[4], crf[4];
        unpack2(cb0, cbf[0], cbf[1]);
        unpack2(cb1, cbf[2], cbf[3]);
        unpack2(cr0, crf[0], crf[1]);
        unpack2(cr1, crf[2], crf[3]);
        #pragma unroll
        for (int k = 0; k < 4; k++) {
            int n = nb0 + k;
            if (n < N) {
                g_ch[(size_t)n * 16 + o] = __float2half(cbf[k]);
                out[(size_t)n * OUT_F + o] = crf[k] + bs;
            }
        }
    }
    __syncthreads();

    // coalesced g copy: 64 nodes x 256B = 1024 uint4
    {
        const uint4* src = (const uint4*)Gs;
        uint4* dst = (uint4*)(g_gh + (size_t)blockIdx.x * NPB * 128);
        #pragma unroll
        for (int kk = 0; kk < 4; kk++) {
            int u = kk * 256 + threadIdx.x;
            int nd = blockIdx.x * NPB + (u >> 4);
            if (nd < N) dst[u] = src[u];
        }
    }
}

// ---------------------------------------------------------------------------
// Kernel 2: per-edge message + scatter, 2 edges per quad-thread (R13 schedule,
// launch_bounds(256,3) for the high-MLP register budget). c table now fp16.
//   msg[o] = c[src,o] + sum_t ea[t]*g[src,t,o]
// ---------------------------------------------------------------------------
__global__ __launch_bounds__(256, 3) void edge_kernel(
    const void* __restrict__ edge_index,       // [2, E] int64 OR int32
    const float* __restrict__ edge_attr,       // [E, 8]
    float* __restrict__ out,
    int E, int halfE)
{
    int tid = blockIdx.x * blockDim.x + threadIdx.x;
    int p = tid >> 2;
    int q = tid & 3;
    if (p >= halfE) return;

    int e0 = p;
    int e1 = p + halfE;
    bool has1 = (e1 < E);
    int e1c = has1 ? e1 : e0;

    int src0, dst0, src1, dst1;
    if (g_idx64) {
        const long long* ei = (const long long*)edge_index;
        src0 = (int)ei[e0];   dst0 = (int)ei[(long)E + e0];
        src1 = (int)ei[e1c];  dst1 = (int)ei[(long)E + e1c];
    } else {
        const int* ei = (const int*)edge_index;
        src0 = ei[e0];        dst0 = ei[E + e0];
        src1 = ei[e1c];       dst1 = ei[E + e1c];
    }

    // issue ALL independent loads first (ea, c, g for both edges)
    const float4* eap = (const float4*)edge_attr;
    float4 a00 = eap[(long)e0 * 2];
    float4 a01 = eap[(long)e0 * 2 + 1];
    float4 a10 = eap[(long)e1c * 2];
    float4 a11 = eap[(long)e1c * 2 + 1];

    const uint2* ch = (const uint2*)g_ch;       // 8B per (node, quad-slot)
    uint2 c0 = ch[src0 * 4 + q];
    uint2 c1 = ch[src1 * 4 + q];

    const uint4* g40 = (const uint4*)(g_gh + (size_t)src0 * 128);
    const uint4* g41 = (const uint4*)(g_gh + (size_t)src1 * 128);
    uint4 u0[4], u1[4];
    #pragma unroll
    for (int j = 0; j < 4; j++) { u0[j] = g40[j * 4 + q]; u1[j] = g41[j * 4 + q]; }

    float2 cA = __half22float2(*(const __half2*)&c0.x);
    float2 cB = __half22float2(*(const __half2*)&c0.y);
    float4 m0 = make_float4(cA.x, cA.y, cB.x, cB.y);
    float2 cC = __half22float2(*(const __half2*)&c1.x);
    float2 cD = __half22float2(*(const __half2*)&c1.y);
    float4 m1 = make_float4(cC.x, cC.y, cD.x, cD.y);

    float ea0[T_F] = {a00.x, a00.y, a00.z, a00.w, a01.x, a01.y, a01.z, a01.w};
    float ea1[T_F] = {a10.x, a10.y, a10.z, a10.w, a11.x, a11.y, a11.z, a11.w};

    #pragma unroll
    for (int j = 0; j < 4; j++) {
        float b0 = ea0[2 * j], b1 = ea0[2 * j + 1];
        float2 pp;
        pp = __half22float2(*(const __half2*)&u0[j].x);
        m0.x = fmaf(b0, pp.x, fmaf(b1, pp.y, m0.x));
        pp = __half22float2(*(const __half2*)&u0[j].y);
        m0.y = fmaf(b0, pp.x, fmaf(b1, pp.y, m0.y));
        pp = __half22float2(*(const __half2*)&u0[j].z);
        m0.z = fmaf(b0, pp.x, fmaf(b1, pp.y, m0.z));
        pp = __half22float2(*(const __half2*)&u0[j].w);
        m0.w = fmaf(b0, pp.x, fmaf(b1, pp.y, m0.w));

        float d0 = ea1[2 * j], d1 = ea1[2 * j + 1];
        pp = __half22float2(*(const __half2*)&u1[j].x);
        m1.x = fmaf(d0, pp.x, fmaf(d1, pp.y, m1.x));
        pp = __half22float2(*(const __half2*)&u1[j].y);
        m1.y = fmaf(d0, pp.x, fmaf(d1, pp.y, m1.y));
        pp = __half22float2(*(const __half2*)&u1[j].z);
        m1.z = fmaf(d0, pp.x, fmaf(d1, pp.y, m1.z));
        pp = __half22float2(*(const __half2*)&u1[j].w);
        m1.w = fmaf(d0, pp.x, fmaf(d1, pp.y, m1.w));
    }

    float* dp0 = out + (size_t)dst0 * OUT_F + q * 4;
    asm volatile("red.global.add.v4.f32 [%0], {%1, %2, %3, %4};"
                 :: "l"(dp0), "f"(m0.x), "f"(m0.y), "f"(m0.z), "f"(m0.w)
                 : "memory");
    if (has1) {
        float* dp1 = out + (size_t)dst1 * OUT_F + q * 4;
        asm volatile("red.global.add.v4.f32 [%0], {%1, %2, %3, %4};"
                     :: "l"(dp1), "f"(m1.x), "f"(m1.y), "f"(m1.z), "f"(m1.w)
                     : "memory");
    }
}

// ---------------------------------------------------------------------------
extern "C" void kernel_launch(void* const* d_in, const int* in_sizes, int n_in,
                              void* d_out, int out_size)
{
    const float* x        = (const float*)d_in[0];
    const void*  eidx     = d_in[1];
    const float* eattr    = (const float*)d_in[2];
    const float* ln_gamma = (const float*)d_in[3];
    const float* ln_beta  = (const float*)d_in[4];
    const float* w_edge   = (const float*)d_in[5];
    const float* b_edge   = (const float*)d_in[6];
    const float* root     = (const float*)d_in[7];
    const float* bias     = (const float*)d_in[8];
    float* out = (float*)d_out;

    int N = in_sizes[0] / IN_F;
    int E = in_sizes[1] / 2;
    int halfE = (E + 1) / 2;

    node_kernel<<<(N + NPB - 1) / NPB, 256>>>(x, ln_gamma, ln_beta, w_edge, b_edge,
                                              root, bias, (const unsigned int*)eidx,
                                              out, N);
    edge_kernel<<<(halfE * 4 + 255) / 256, 256>>>(eidx, eattr, out, E, halfE);
}

// round 16
// speedup vs baseline: 2.7875x; 1.6235x over previous
#include <cuda_runtime.h>
#include <cuda_bf16.h>
#include <cuda_fp16.h>

// Problem constants (EdgeConv_33930241638504): N=50000, E=800000, IN=OUT=16, T=8
#define MAXN 50048
#define IN_F 16
#define OUT_F 16
#define T_F 8
#define LN_EPS 1e-5f

// Scratch (device globals: allocation-free rule)
// g fp16, 256B/node, layout [n][j=t/2][o][s=t&1]: half idx = n*128 + j*32 + o*2 + s.
__device__ __half g_gh[(size_t)MAXN * 128];   // 12.8 MB (L2-resident)
__device__ __half g_ch[(size_t)MAXN * 16];    // c[n][o] fp16 (1.6 MB, L2-resident)
__device__ int    g_idx64;                    // 1 if edge_index int64, 0 if int32

// ---------------------------------------------------------------------------
// Kernel 1: per-node preprocessing, 4 nodes per 16-lane group (register-blocked).
//   g[n,t,o] = sum_i h[i]*W[t,i,o]    (fp16, staged via smem -> coalesced copy)
//   c[n,o]   = sum_i h[i]*b_edge[i,o] (fp16 table)
//   out[n,o] = sum_i h[i]*root[i,o] + bias[o]
// W/B/R transposed in smem to [t][o][i] (pad 20); each W-row LDS.128 serves 4 nodes.
// ---------------------------------------------------------------------------
#define OPAD 20
#define NPB 64   // nodes per block
__global__ __launch_bounds__(256, 2) void node_kernel(
    const float* __restrict__ x,
    const float* __restrict__ ln_gamma,
    const float* __restrict__ ln_beta,
    const float* __restrict__ w_edge,   // [T, IN*OUT] = 2048 floats
    const float* __restrict__ b_edge,   // [IN*OUT]
    const float* __restrict__ root,     // [IN, OUT]
    const float* __restrict__ bias,     // [OUT]
    const unsigned int* __restrict__ idx_raw,
    float* __restrict__ out,
    int N)
{
    __shared__ float Wt[T_F * IN_F * OPAD];   // [t][o*20 + i]  10 KB
    __shared__ float Bt[IN_F * OPAD];
    __shared__ float Rt[IN_F * OPAD];
    __shared__ __half Gs[NPB * 128];          // 16 KB staged g for 64 nodes

    for (int idx = threadIdx.x; idx < T_F * IN_F * OUT_F; idx += blockDim.x) {
        int t = idx >> 8, rem = idx & 255, i = rem >> 4, o = rem & 15;
        Wt[t * (IN_F * OPAD) + o * OPAD + i] = w_edge[idx];
    }
    for (int idx = threadIdx.x; idx < IN_F * OUT_F; idx += blockDim.x) {
        int i = idx >> 4, o = idx & 15;
        Bt[o * OPAD + i] = b_edge[idx];
        Rt[o * OPAD + i] = root[idx];
    }

    // dtype detection (block 0, warp 0): int64 LE with values < N => odd words zero.
    if (blockIdx.x == 0 && threadIdx.x < 32) {
        int lane = threadIdx.x;
        unsigned int any = 0;
        #pragma unroll
        for (int k = 0; k < 8; k++) any |= idx_raw[2 * (lane * 8 + k) + 1];
        unsigned int ballot = __ballot_sync(0xffffffffu, any != 0);
        if (lane == 0) g_idx64 = (ballot == 0u) ? 1 : 0;
    }
    __syncthreads();

    int gidx = threadIdx.x >> 4;        // group 0..15
    int o    = threadIdx.x & 15;        // lane within group = output/feature idx
    int nb0  = blockIdx.x * NPB + gidx * 4;   // group's first node

    // LN for the group's 4 nodes
    float h_own[4];
    #pragma unroll
    for (int k = 0; k < 4; k++) {
        int n = nb0 + k;
        if (n >= N) n = N - 1;
        float xv = x[(size_t)n * IN_F + o];
        float s = xv;
        #pragma unroll
        for (int off = 8; off > 0; off >>= 1) s += __shfl_xor_sync(0xffffffffu, s, off, 16);
        float mu = s * (1.0f / 16.0f);
        float d = xv - mu;
        float v = d * d;
        #pragma unroll
        for (int off = 8; off > 0; off >>= 1) v += __shfl_xor_sync(0xffffffffu, v, off, 16);
        float rstd = rsqrtf(v * (1.0f / 16.0f) + LN_EPS);
        float h = d * rstd * ln_gamma[o] + ln_beta[o];
        h_own[k] = fmaxf(h, 0.0f);
    }

    // full h vectors for the 4 nodes in registers
    float hv[4][IN_F];
    #pragma unroll
    for (int k = 0; k < 4; k++) {
        #pragma unroll
        for (int i = 0; i < IN_F; i++)
            hv[k][i] = __shfl_sync(0xffffffffu, h_own[k], i, 16);
    }

    // g: each W-row load serves 4 nodes
    #pragma unroll
    for (int t = 0; t < T_F; t++) {
        const float4* wrow = (const float4*)&Wt[t * (IN_F * OPAD) + o * OPAD];
        float4 w0 = wrow[0], w1 = wrow[1], w2 = wrow[2], w3 = wrow[3];
        #pragma unroll
        for (int k = 0; k < 4; k++) {
            float acc = 0.0f;
            acc = fmaf(hv[k][0],  w0.x, acc); acc = fmaf(hv[k][1],  w0.y, acc);
            acc = fmaf(hv[k][2],  w0.z, acc); acc = fmaf(hv[k][3],  w0.w, acc);
            acc = fmaf(hv[k][4],  w1.x, acc); acc = fmaf(hv[k][5],  w1.y, acc);
            acc = fmaf(hv[k][6],  w1.z, acc); acc = fmaf(hv[k][7],  w1.w, acc);
            acc = fmaf(hv[k][8],  w2.x, acc); acc = fmaf(hv[k][9],  w2.y, acc);
            acc = fmaf(hv[k][10], w2.z, acc); acc = fmaf(hv[k][11], w2.w, acc);
            acc = fmaf(hv[k][12], w3.x, acc); acc = fmaf(hv[k][13], w3.y, acc);
            acc = fmaf(hv[k][14], w3.z, acc); acc = fmaf(hv[k][15], w3.w, acc);
            Gs[(gidx * 4 + k) * 128 + (t >> 1) * 32 + o * 2 + (t & 1)] = __float2half(acc);
        }
    }

    // c (fp16 table) and out (fp32)
    {
        const float4* brow = (const float4*)&Bt[o * OPAD];
        float4 b0 = brow[0], b1 = brow[1], b2 = brow[2], b3 = brow[3];
        const float4* rrow = (const float4*)&Rt[o * OPAD];
        float4 r0 = rrow[0], r1 = rrow[1], r2 = rrow[2], r3 = rrow[3];
        float bs = bias[o];
        #pragma unroll
        for (int k = 0; k < 4; k++) {
            int n = nb0 + k;
            bool valid = (n < N);
            float cb = 0.0f, cr = bs;
            cb = fmaf(hv[k][0],  b0.x, cb); cr = fmaf(hv[k][0],  r0.x, cr);
            cb = fmaf(hv[k][1],  b0.y, cb); cr = fmaf(hv[k][1],  r0.y, cr);
            cb = fmaf(hv[k][2],  b0.z, cb); cr = fmaf(hv[k][2],  r0.z, cr);
            cb = fmaf(hv[k][3],  b0.w, cb); cr = fmaf(hv[k][3],  r0.w, cr);
            cb = fmaf(hv[k][4],  b1.x, cb); cr = fmaf(hv[k][4],  r1.x, cr);
            cb = fmaf(hv[k][5],  b1.y, cb); cr = fmaf(hv[k][5],  r1.y, cr);
            cb = fmaf(hv[k][6],  b1.z, cb); cr = fmaf(hv[k][6],  r1.z, cr);
            cb = fmaf(hv[k][7],  b1.w, cb); cr = fmaf(hv[k][7],  r1.w, cr);
            cb = fmaf(hv[k][8],  b2.x, cb); cr = fmaf(hv[k][8],  r2.x, cr);
            cb = fmaf(hv[k][9],  b2.y, cb); cr = fmaf(hv[k][9],  r2.y, cr);
            cb = fmaf(hv[k][10], b2.z, cb); cr = fmaf(hv[k][10], r2.z, cr);
            cb = fmaf(hv[k][11], b2.w, cb); cr = fmaf(hv[k][11], r2.w, cr);
            cb = fmaf(hv[k][12], b3.x, cb); cr = fmaf(hv[k][12], r3.x, cr);
            cb = fmaf(hv[k][13], b3.y, cb); cr = fmaf(hv[k][13], r3.y, cr);
            cb = fmaf(hv[k][14], b3.z, cb); cr = fmaf(hv[k][14], r3.z, cr);
            cb = fmaf(hv[k][15], b3.w, cb); cr = fmaf(hv[k][15], r3.w, cr);
            if (valid) {
                g_ch[(size_t)n * 16 + o] = __float2half(cb);
                out[(size_t)n * OUT_F + o] = cr;
            }
        }
    }
    __syncthreads();

    // coalesced g copy: 64 nodes x 256B = 1024 uint4
    {
        const uint4* src = (const uint4*)Gs;
        uint4* dst = (uint4*)(g_gh + (size_t)blockIdx.x * NPB * 128);
        #pragma unroll
        for (int kk = 0; kk < 4; kk++) {
            int u = kk * 256 + threadIdx.x;
            int nd = blockIdx.x * NPB + (u >> 4);
            if (nd < N) dst[u] = src[u];
        }
    }
}

// ---------------------------------------------------------------------------
// Kernel 2: per-edge message + scatter, 2 edges per quad-thread.
// __launch_bounds__(256, 3): high register budget keeps all 8 g-gathers +
// 2 c + 2 ea in flight. c table fp16 (-32B/edge on the LTS-capped stream).
//   msg[o] = c[src,o] + sum_t ea[t]*g[src,t,o]
// ---------------------------------------------------------------------------
__global__ __launch_bounds__(256, 3) void edge_kernel(
    const void* __restrict__ edge_index,       // [2, E] int64 OR int32
    const float* __restrict__ edge_attr,       // [E, 8]
    float* __restrict__ out,
    int E, int halfE)
{
    int tid = blockIdx.x * blockDim.x + threadIdx.x;
    int p = tid >> 2;
    int q = tid & 3;
    if (p >= halfE) return;

    int e0 = p;
    int e1 = p + halfE;
    bool has1 = (e1 < E);
    int e1c = has1 ? e1 : e0;

    int src0, dst0, src1, dst1;
    if (g_idx64) {
        const long long* ei = (const long long*)edge_index;
        src0 = (int)ei[e0];   dst0 = (int)ei[(long)E + e0];
        src1 = (int)ei[e1c];  dst1 = (int)ei[(long)E + e1c];
    } else {
        const int* ei = (const int*)edge_index;
        src0 = ei[e0];        dst0 = ei[E + e0];
        src1 = ei[e1c];       dst1 = ei[E + e1c];
    }

    // issue ALL independent loads first (ea, c, g for both edges)
    const float4* eap = (const float4*)edge_attr;
    float4 a00 = eap[(long)e0 * 2];
    float4 a01 = eap[(long)e0 * 2 + 1];
    float4 a10 = eap[(long)e1c * 2];
    float4 a11 = eap[(long)e1c * 2 + 1];

    const uint2* ch = (const uint2*)g_ch;       // 8B per (node, quad-slot)
    uint2 c0 = ch[src0 * 4 + q];
    uint2 c1 = ch[src1 * 4 + q];

    const uint4* g40 = (const uint4*)(g_gh + (size_t)src0 * 128);
    const uint4* g41 = (const uint4*)(g_gh + (size_t)src1 * 128);
    uint4 u0[4], u1[4];
    #pragma unroll
    for (int j = 0; j < 4; j++) { u0[j] = g40[j * 4 + q]; u1[j] = g41[j * 4 + q]; }

    float2 cA = __half22float2(*(const __half2*)&c0.x);
    float2 cB = __half22float2(*(const __half2*)&c0.y);
    float4 m0 = make_float4(cA.x, cA.y, cB.x, cB.y);
    float2 cC = __half22float2(*(const __half2*)&c1.x);
    float2 cD = __half22float2(*(const __half2*)&c1.y);
    float4 m1 = make_float4(cC.x, cC.y, cD.x, cD.y);

    float ea0[T_F] = {a00.x, a00.y, a00.z, a00.w, a01.x, a01.y, a01.z, a01.w};
    float ea1[T_F] = {a10.x, a10.y, a10.z, a10.w, a11.x, a11.y, a11.z, a11.w};

    #pragma unroll
    for (int j = 0; j < 4; j++) {
        float b0 = ea0[2 * j], b1 = ea0[2 * j + 1];
        float2 pp;
        pp = __half22float2(*(const __half2*)&u0[j].x);
        m0.x = fmaf(b0, pp.x, fmaf(b1, pp.y, m0.x));
        pp = __half22float2(*(const __half2*)&u0[j].y);
        m0.y = fmaf(b0, pp.x, fmaf(b1, pp.y, m0.y));
        pp = __half22float2(*(const __half2*)&u0[j].z);
        m0.z = fmaf(b0, pp.x, fmaf(b1, pp.y, m0.z));
        pp = __half22float2(*(const __half2*)&u0[j].w);
        m0.w = fmaf(b0, pp.x, fmaf(b1, pp.y, m0.w));

        float d0 = ea1[2 * j], d1 = ea1[2 * j + 1];
        pp = __half22float2(*(const __half2*)&u1[j].x);
        m1.x = fmaf(d0, pp.x, fmaf(d1, pp.y, m1.x));
        pp = __half22float2(*(const __half2*)&u1[j].y);
        m1.y = fmaf(d0, pp.x, fmaf(d1, pp.y, m1.y));
        pp = __half22float2(*(const __half2*)&u1[j].z);
        m1.z = fmaf(d0, pp.x, fmaf(d1, pp.y, m1.z));
        pp = __half22float2(*(const __half2*)&u1[j].w);
        m1.w = fmaf(d0, pp.x, fmaf(d1, pp.y, m1.w));
    }

    float* dp0 = out + (size_t)dst0 * OUT_F + q * 4;
    asm volatile("red.global.add.v4.f32 [%0], {%1, %2, %3, %4};"
                 :: "l"(dp0), "f"(m0.x), "f"(m0.y), "f"(m0.z), "f"(m0.w)
                 : "memory");
    if (has1) {
        float* dp1 = out + (size_t)dst1 * OUT_F + q * 4;
        asm volatile("red.global.add.v4.f32 [%0], {%1, %2, %3, %4};"
                     :: "l"(dp1), "f"(m1.x), "f"(m1.y), "f"(m1.z), "f"(m1.w)
                     : "memory");
    }
}

// ---------------------------------------------------------------------------
extern "C" void kernel_launch(void* const* d_in, const int* in_sizes, int n_in,
                              void* d_out, int out_size)
{
    const float* x        = (const float*)d_in[0];
    const void*  eidx     = d_in[1];
    const float* eattr    = (const float*)d_in[2];
    const float* ln_gamma = (const float*)d_in[3];
    const float* ln_beta  = (const float*)d_in[4];
    const float* w_edge   = (const float*)d_in[5];
    const float* b_edge   = (const float*)d_in[6];
    const float* root     = (const float*)d_in[7];
    const float* bias     = (const float*)d_in[8];
    float* out = (float*)d_out;

    int N = in_sizes[0] / IN_F;
    int E = in_sizes[1] / 2;
    int halfE = (E + 1) / 2;

    node_kernel<<<(N + NPB - 1) / NPB, 256>>>(x, ln_gamma, ln_beta, w_edge, b_edge,
                                              root, bias, (const unsigned int*)eidx,
                                              out, N);
    edge_kernel<<<(halfE * 4 + 255) / 256, 256>>>(eidx, eattr, out, E, halfE);
}